// round 1
// baseline (speedup 1.0000x reference)
#include <cuda_runtime.h>

// EMA scan: s_t = (1-ALPHA)*x_t + ALPHA*s_{t-1}
// x: (T=1024, C=32*1024) fp32, state: (C,) fp32
// out: (T, C) fp32 [+ optional final_state (C,) appended in d_out]

#define ALPHA_F 0.9f
#define UNROLL 16

__global__ void ema_scan_kernel(const float* __restrict__ x,
                                const float* __restrict__ state,
                                float* __restrict__ out,
                                float* __restrict__ final_state,
                                int C, int T) {
    int c = blockIdx.x * blockDim.x + threadIdx.x;
    if (c >= C) return;

    const float beta = 1.0f - ALPHA_F;   // matches reference's (1.0 - ALPHA) rounding
    float s = state[c];

    const float* __restrict__ xp = x + c;
    float* __restrict__ op = out + c;

    // T is a multiple of UNROLL (1024 / 16). Batch 16 independent loads to get
    // MLP=16 per thread (latency-BW: ~7 warps/SM * 16 * 128B / ~380cyc covers
    // the ~42 B/cyc/SM needed to saturate chip memory BW).
    for (int t0 = 0; t0 < T; t0 += UNROLL) {
        float v[UNROLL];
        size_t base = (size_t)t0 * (size_t)C;
        #pragma unroll
        for (int i = 0; i < UNROLL; i++) {
            v[i] = xp[base + (size_t)i * (size_t)C];
        }
        #pragma unroll
        for (int i = 0; i < UNROLL; i++) {
            s = v[i] * beta + s * ALPHA_F;
            op[base + (size_t)i * (size_t)C] = s;
        }
    }

    if (final_state) final_state[c] = s;
}

extern "C" void kernel_launch(void* const* d_in, const int* in_sizes, int n_in,
                              void* d_out, int out_size) {
    const float* x     = (const float*)d_in[0];
    const float* state = (const float*)d_in[1];
    float* out = (float*)d_out;

    int x_elems = in_sizes[0];         // T * C
    int C = in_sizes[1];               // 32 * 1024
    int T = x_elems / C;               // 1024

    // If out_size includes the final_state tail, write it after the out tensor.
    float* final_state = (out_size > x_elems) ? (out + x_elems) : nullptr;

    int threads = 256;
    int blocks = (C + threads - 1) / threads;
    ema_scan_kernel<<<blocks, threads>>>(x, state, out, final_state, C, T);
}

// round 2
// speedup vs baseline: 1.1114x; 1.1114x over previous
#include <cuda_runtime.h>

// EMA scan: s_t = (1-ALPHA)*x_t + ALPHA*s_{t-1}
// x: (T=1024, C=32*1024) fp32, state: (C,), out: (T, C) [+ final_state (C,)]
//
// Time-parallel exact decomposition:
//   s_i = alpha^{i+1} * s_in + sum_{j<=i} beta * alpha^{i-j} * x_j
// Block = 32 channels x 32 time-chunks of 32 steps. Chunk partials composed
// via an in-warp Kogge-Stone affine scan (A = alpha^32 const).

#define ALPHA_F 0.9f
#define NCHUNK 32
#define LCHUNK 32        // T = NCHUNK * LCHUNK = 1024

__global__ __launch_bounds__(1024, 1)
void ema_scan_par(const float* __restrict__ x,
                  const float* __restrict__ state,
                  float* __restrict__ out,
                  float* __restrict__ final_state,
                  int C) {
    __shared__ float sp[NCHUNK][33];   // padded: conflict-free both orientations

    const int lane = threadIdx.x;      // channel within block (also warp lane)
    const int w    = threadIdx.y;      // time chunk (also warp id)
    const int c    = blockIdx.x * 32 + lane;

    const float a = ALPHA_F;
    const float b = 1.0f - ALPHA_F;

    // ---- Phase 1: coalesced loads (MLP=32) + zero-init local scan ----
    const float* __restrict__ xp = x + (size_t)(w * LCHUNK) * (size_t)C + c;
    float v[LCHUNK];
    #pragma unroll
    for (int i = 0; i < LCHUNK; i++) v[i] = xp[(size_t)i * (size_t)C];

    float s = 0.0f;
    #pragma unroll
    for (int i = 0; i < LCHUNK; i++) { s = v[i] * b + s * a; v[i] = s; }

    sp[w][lane] = s;                   // chunk partial (zero-init final value)
    __syncthreads();

    // ---- Phase 2: warp w scans the 32 chunk maps for channel (block, w) ----
    {
        float p = sp[lane][w];         // partial of chunk 'lane', channel w

        float aL = 1.0f;               // alpha^LCHUNK, const-folded
        #pragma unroll
        for (int i = 0; i < LCHUNK; i++) aL *= a;

        // inclusive affine scan: map s -> Acc*s + Bcc over chunks [0..lane]
        float Acc = aL, Bcc = p;
        #pragma unroll
        for (int d = 1; d < NCHUNK; d <<= 1) {
            float Au = __shfl_up_sync(0xffffffffu, Acc, d);
            float Bu = __shfl_up_sync(0xffffffffu, Bcc, d);
            if (lane >= d) { Bcc = Acc * Bu + Bcc; Acc = Acc * Au; }
        }

        float s0   = state[blockIdx.x * 32 + w];
        float sout = Acc * s0 + Bcc;               // state after chunk 'lane'
        float sin_ = __shfl_up_sync(0xffffffffu, sout, 1);
        if (lane == 0) sin_ = s0;                  // exclusive: input state

        sp[lane][w] = sin_;
    }
    __syncthreads();

    // ---- Phase 3: fix up with incoming state, coalesced stores ----
    {
        float sin_ = sp[w][lane];
        float* __restrict__ op = out + (size_t)(w * LCHUNK) * (size_t)C + c;
        float pw = a * sin_;           // alpha^{i+1} * s_in, i = 0
        float olast = 0.0f;
        #pragma unroll
        for (int i = 0; i < LCHUNK; i++) {
            float o = v[i] + pw;
            op[(size_t)i * (size_t)C] = o;
            pw *= a;
            olast = o;
        }
        if (final_state && w == NCHUNK - 1) final_state[c] = olast;
    }
}

// Fallback: one thread per channel (any T, any C)
__global__ void ema_scan_fallback(const float* __restrict__ x,
                                  const float* __restrict__ state,
                                  float* __restrict__ out,
                                  float* __restrict__ final_state,
                                  int C, int T) {
    int c = blockIdx.x * blockDim.x + threadIdx.x;
    if (c >= C) return;
    const float a = ALPHA_F, b = 1.0f - ALPHA_F;
    float s = state[c];
    for (int t = 0; t < T; t++) {
        s = x[(size_t)t * C + c] * b + s * a;
        out[(size_t)t * C + c] = s;
    }
    if (final_state) final_state[c] = s;
}

extern "C" void kernel_launch(void* const* d_in, const int* in_sizes, int n_in,
                              void* d_out, int out_size) {
    const float* x     = (const float*)d_in[0];
    const float* state = (const float*)d_in[1];
    float* out = (float*)d_out;

    int x_elems = in_sizes[0];         // T * C
    int C = in_sizes[1];               // 32 * 1024
    int T = x_elems / C;               // 1024

    float* final_state = (out_size > x_elems) ? (out + x_elems) : nullptr;

    if (T == NCHUNK * LCHUNK && (C % 32) == 0) {
        dim3 block(32, NCHUNK);
        dim3 grid(C / 32);
        ema_scan_par<<<grid, block>>>(x, state, out, final_state, C);
    } else {
        int threads = 256;
        int blocks = (C + threads - 1) / threads;
        ema_scan_fallback<<<blocks, threads>>>(x, state, out, final_state, C, T);
    }
}

// round 3
// speedup vs baseline: 1.5306x; 1.3772x over previous
#include <cuda_runtime.h>

// EMA scan: s_t = (1-ALPHA)*x_t + ALPHA*s_{t-1}
// x: (T=1024, C=32*1024) fp32, state: (C,), out: (T, C) [+ final_state (C,)]
//
// Exact time-parallel decomposition, geometry chosen for 2 resident blocks/SM:
//   block = 512 threads, covers 16 channels x full T.
//   warp lane -> (sub = lane/16 in {0,1}, ch = lane%16)
//   chunk = warpId*2 + sub  (32 chunks of 32 steps)
// Phase 1: each thread zero-init scans its 32-step chunk (64B coalesced segs).
// Phase 2: warp w Kogge-Stone affine-scans the 32 chunk maps of channel w.
// Phase 3: out_i = v[i] + alpha^{i+1} * s_in, coalesced streaming stores.

#define ALPHA_F 0.9f
#define NCHUNK 32
#define LCHUNK 32          // T = 1024
#define CH_BLK 16          // channels per block
#define NWARP  16          // warps per block

__global__ __launch_bounds__(512, 2)
void ema_scan_par(const float* __restrict__ x,
                  const float* __restrict__ state,
                  float* __restrict__ out,
                  float* __restrict__ final_state,
                  int C) {
    __shared__ float sp[NCHUNK][CH_BLK + 1];   // +1 pad: conflict-free both ways

    const int tid  = threadIdx.x;
    const int wid  = tid >> 5;
    const int lane = tid & 31;
    const int sub  = lane >> 4;        // which of the warp's two chunks
    const int ch   = lane & 15;        // channel within block
    const int chunk = wid * 2 + sub;
    const int c    = blockIdx.x * CH_BLK + ch;

    const float a = ALPHA_F;
    const float b = 1.0f - ALPHA_F;

    // Prefetch the state this thread's warp needs in phase 2 (warp w -> channel w).
    // Issued before the load burst; latency fully hidden.
    float s0_pref = state[blockIdx.x * CH_BLK + wid];

    // ---- Phase 1: loads (MLP=32) + zero-init local scan ----
    const float* __restrict__ xp = x + chunk * LCHUNK * C + c;
    float v[LCHUNK];
    #pragma unroll
    for (int i = 0; i < LCHUNK; i++) v[i] = __ldcs(xp + i * C);

    float s = 0.0f;
    #pragma unroll
    for (int i = 0; i < LCHUNK; i++) { s = v[i] * b + s * a; v[i] = s; }

    sp[chunk][ch] = s;
    __syncthreads();

    // ---- Phase 2: warp w scans 32 chunk maps of channel w (lane = chunk) ----
    {
        float p = sp[lane][wid];

        float aL = 1.0f;               // alpha^LCHUNK (const-folded)
        #pragma unroll
        for (int i = 0; i < LCHUNK; i++) aL *= a;

        float Acc = aL, Bcc = p;       // inclusive affine scan over chunks [0..lane]
        #pragma unroll
        for (int d = 1; d < NCHUNK; d <<= 1) {
            float Au = __shfl_up_sync(0xffffffffu, Acc, d);
            float Bu = __shfl_up_sync(0xffffffffu, Bcc, d);
            if (lane >= d) { Bcc = Acc * Bu + Bcc; Acc = Acc * Au; }
        }

        float sout = Acc * s0_pref + Bcc;            // state after chunk 'lane'
        float sin_ = __shfl_up_sync(0xffffffffu, sout, 1);
        if (lane == 0) sin_ = s0_pref;               // exclusive: incoming state

        sp[lane][wid] = sin_;
    }
    __syncthreads();

    // ---- Phase 3: fix up, streaming stores ----
    {
        float sin_ = sp[chunk][ch];
        float* __restrict__ op = out + chunk * LCHUNK * C + c;
        float pw = a * sin_;
        float olast = 0.0f;
        #pragma unroll
        for (int i = 0; i < LCHUNK; i++) {
            float o = v[i] + pw;
            __stcs(op + i * C, o);
            pw *= a;
            olast = o;
        }
        if (final_state && chunk == NCHUNK - 1) final_state[c] = olast;
    }
}

// Fallback: one thread per channel (any T, any C)
__global__ void ema_scan_fallback(const float* __restrict__ x,
                                  const float* __restrict__ state,
                                  float* __restrict__ out,
                                  float* __restrict__ final_state,
                                  int C, int T) {
    int c = blockIdx.x * blockDim.x + threadIdx.x;
    if (c >= C) return;
    const float a = ALPHA_F, b = 1.0f - ALPHA_F;
    float s = state[c];
    for (int t = 0; t < T; t++) {
        s = x[(size_t)t * C + c] * b + s * a;
        out[(size_t)t * C + c] = s;
    }
    if (final_state) final_state[c] = s;
}

extern "C" void kernel_launch(void* const* d_in, const int* in_sizes, int n_in,
                              void* d_out, int out_size) {
    const float* x     = (const float*)d_in[0];
    const float* state = (const float*)d_in[1];
    float* out = (float*)d_out;

    int x_elems = in_sizes[0];         // T * C
    int C = in_sizes[1];               // 32 * 1024
    int T = x_elems / C;               // 1024

    float* final_state = (out_size > x_elems) ? (out + x_elems) : nullptr;

    if (T == NCHUNK * LCHUNK && (C % CH_BLK) == 0) {
        ema_scan_par<<<C / CH_BLK, 512>>>(x, state, out, final_state, C);
    } else {
        int threads = 256;
        int blocks = (C + threads - 1) / threads;
        ema_scan_fallback<<<blocks, threads>>>(x, state, out, final_state, C, T);
    }
}